// round 13
// baseline (speedup 1.0000x reference)
#include <cuda_runtime.h>
#include <cuda_fp16.h>
#include <math.h>

// Fixed problem shapes (from setup_inputs)
#define NN   80000
#define NN1  40000
#define NN2  20000
#define NB   16

// ---------------- scratch (device globals; no allocation allowed) ----------------
// Everything needing per-run init is zero-fill (empty max-pool encoding = 0x0),
// packed in one struct cleared by a single cudaMemsetAsync.
struct Scratch {
    float    agg1[NN * 8];
    unsigned cnt1[NN];
    unsigned x1enc[NN1 * 8];
    int      batch1[NN1];
    float    agg2[NN1 * 16];
    unsigned cnt2[NN1];
    unsigned x2enc[NN2 * 16];
    int      batch2[NN2];
    float    gsum[NB * 16];
    unsigned gcnt[NB];
};
__device__ __align__(16) Scratch g_s;
__device__ __align__(16) float g_x1[NN1 * 8];   // fully written by k_xw2
// xW2 in e4m3, pair-duplicated layout: per node 576B = 9 groups (g = k1 + 3*k2) x 64B.
// Group layout: [p in {0,1}] x 32B where pair p covers corners k0 = p and p+1:
//   bytes p*32 + h*16 + c*8 + j  = e4m3( xw2[n1][3g + p + c][8h + j] ),  h,c in {0,1}, j in 0..7
__device__ __align__(32) unsigned char g_xw2q[(size_t)NN1 * 576];   // 23 MB (L2-resident)

// ---------------- helpers ----------------
__device__ __forceinline__ float elu1(float v) { return v > 0.0f ? v : expm1f(v); }

// order-preserving float <-> uint encoding for atomicMax on floats (0x0 = empty -> 0.0)
__device__ __forceinline__ unsigned fenc(float f) {
    unsigned u = __float_as_uint(f);
    return (u & 0x80000000u) ? ~u : (u | 0x80000000u);
}
__device__ __forceinline__ float fdec0(unsigned u) {
    if (u == 0u) return 0.0f;
    return (u & 0x80000000u) ? __uint_as_float(u & 0x7fffffffu) : __uint_as_float(~u);
}

__device__ __forceinline__ __half2 u2h2(unsigned u) {
    return *reinterpret_cast<__half2*>(&u);
}

__device__ __forceinline__ void red_add_v4(float* addr, float a, float b, float c, float d) {
    asm volatile("red.global.add.v4.f32 [%0], {%1, %2, %3, %4};"
                 :: "l"(addr), "f"(a), "f"(b), "f"(c), "f"(d) : "memory");
}

// pack two floats to e4m3x2 (16-bit): low byte = lo, high byte = hi
__device__ __forceinline__ unsigned short enc_e4m3x2(float hi, float lo) {
    unsigned short r;
    asm("{ .reg .b16 t; cvt.rn.satfinite.e4m3x2.f32 t, %1, %2; mov.b16 %0, t; }"
        : "=h"(r) : "f"(hi), "f"(lo));
    return r;
}

// decode 4 e4m3 (one 32-bit word) and accumulate m[0..3] += s * val
__device__ __forceinline__ void acc_fp8_word(float* m, unsigned w, float s) {
    unsigned lo2, hi2;
    asm("{ .reg .b16 l, h; mov.b32 {l, h}, %2;\n\t"
        "cvt.rn.f16x2.e4m3x2 %0, l; cvt.rn.f16x2.e4m3x2 %1, h; }"
        : "=r"(lo2), "=r"(hi2) : "r"(w));
    float2 a = __half22float2(u2h2(lo2));
    float2 b = __half22float2(u2h2(hi2));
    m[0] += s * a.x; m[1] += s * a.y; m[2] += s * b.x; m[3] += s * b.y;
}

// B-spline (degree 1, K=3) fractional parts + base indices from pseudo coords
__device__ __forceinline__ void spline_coords_ldcs(const float* __restrict__ attr, int e,
                                                   float f[3], int i0[3]) {
#pragma unroll
    for (int d = 0; d < 3; d++) {
        float v  = __ldcs(attr + 3 * (size_t)e + d) * 2.0f;   // pseudo * (K-1)
        float fl = floorf(v);
        fl = fminf(fmaxf(fl, 0.0f), 1.0f);                    // clip to [0, K-2]
        i0[d] = (int)fl;
        f[d]  = v - fl;
    }
}

// ---------------- kernels ----------------
// Level-1 edge kernel: msg[o] = sum_s basis_s * (x[src] . W1[k_s][:,o]); scatter-add to agg1[dst]
__global__ void k_edge1(const int* __restrict__ ei, const float* __restrict__ attr,
                        const float* __restrict__ x, const float* __restrict__ W1, int E) {
    __shared__ float Ws[27 * 17];
    for (int j = threadIdx.x; j < 432; j += blockDim.x)
        Ws[(j >> 4) * 17 + (j & 15)] = W1[j];
    __syncthreads();

    int e = blockIdx.x * blockDim.x + threadIdx.x;
    if (e >= E) return;
    int src = __ldcs(ei + e), dst = __ldcs(ei + E + e);

    float f[3]; int i0[3];
    spline_coords_ldcs(attr, e, f, i0);

    float2 xv = *(const float2*)(x + 2 * (size_t)src);

    float msg[8];
#pragma unroll
    for (int o = 0; o < 8; o++) msg[o] = 0.0f;

#pragma unroll
    for (int s = 0; s < 8; s++) {
        int b0 = s & 1, b1 = (s >> 1) & 1, b2 = (s >> 2) & 1;
        float w = (b0 ? f[0] : 1.0f - f[0]) * (b1 ? f[1] : 1.0f - f[1]) * (b2 ? f[2] : 1.0f - f[2]);
        int k = (i0[0] + b0) + 3 * (i0[1] + b1) + 9 * (i0[2] + b2);
        const float* wp = Ws + k * 17;
        float wx = w * xv.x, wy = w * xv.y;
#pragma unroll
        for (int o = 0; o < 8; o++) msg[o] += wx * wp[o] + wy * wp[8 + o];
    }
    float* a = g_s.agg1 + (size_t)dst * 8;
    red_add_v4(a,     msg[0], msg[1], msg[2], msg[3]);
    red_add_v4(a + 4, msg[4], msg[5], msg[6], msg[7]);
    atomicAdd(&g_s.cnt1[dst], 1u);
}

// Level-1 node kernel: h = elu(agg/cnt + x@root1 + b1); max-pool into cluster1 bins.
// Also aggregates cnt1 -> cnt2.
__global__ void k_node1(const float* __restrict__ x, const float* __restrict__ root1,
                        const float* __restrict__ b1, const int* __restrict__ batch,
                        const int* __restrict__ cl1, int N) {
    int n = blockIdx.x * blockDim.x + threadIdx.x;
    if (n >= N) return;
    const float4* ar = (const float4*)(g_s.agg1 + (size_t)n * 8);
    float4 a0 = ar[0], a1 = ar[1];
    float ag[8] = {a0.x, a0.y, a0.z, a0.w, a1.x, a1.y, a1.z, a1.w};
    unsigned c1 = g_s.cnt1[n];
    float inv = 1.0f / fmaxf((float)c1, 1.0f);
    float2 xv = *(const float2*)(x + 2 * (size_t)n);
    int c = cl1[n];
#pragma unroll
    for (int o = 0; o < 8; o++) {
        float h = ag[o] * inv + xv.x * __ldg(root1 + o) + xv.y * __ldg(root1 + 8 + o) + __ldg(b1 + o);
        h = elu1(h);
        atomicMax(&g_s.x1enc[(size_t)c * 8 + o], fenc(h));
    }
    atomicMax(&g_s.batch1[c], batch[n]);
    if (c1) atomicAdd(&g_s.cnt2[c], c1);
}

// Decode x1 + precompute xW2 in e4m3 with pair-duplicated layout.
// 8 threads/node compute; staged via shared (packed e4m3x2 per (k,q)), then
// coalesced STG.128 of the duplicated 576B node rows.
__global__ void k_xw2(const float* __restrict__ W2, int N1) {
    __shared__ float Ws[3456];
    __shared__ __align__(16) unsigned short sp[32 * 216];   // [node][k][q] e4m3x2
    for (int j = threadIdx.x; j < 3456; j += blockDim.x) Ws[j] = W2[j];
    __syncthreads();

    int local = threadIdx.x >> 3;
    int n1 = blockIdx.x * 32 + local;
    int q  = threadIdx.x & 7;
    if (n1 < N1) {
        float xv[8];
#pragma unroll
        for (int c = 0; c < 8; c++)
            xv[c] = fdec0(g_s.x1enc[(size_t)n1 * 8 + c]);
        if (q < 4)   // decoded x1 for k_node2's root term
            *(float2*)(g_x1 + (size_t)n1 * 8 + 2 * q) = make_float2(xv[2 * q], xv[2 * q + 1]);

        int o0 = 2 * q;
#pragma unroll
        for (int k = 0; k < 27; k++) {
            float acc0 = 0.0f, acc1 = 0.0f;
#pragma unroll
            for (int c = 0; c < 8; c++) {
                acc0 += xv[c] * Ws[k * 128 + c * 16 + o0];
                acc1 += xv[c] * Ws[k * 128 + c * 16 + o0 + 1];
            }
            sp[local * 216 + k * 8 + q] = enc_e4m3x2(acc1, acc0);   // low byte = out 2q
        }
    }
    __syncthreads();

    // write duplicated layout: per node 36 uint4 (576B)
    int nodes = N1 - blockIdx.x * 32; if (nodes > 32) nodes = 32;
    int total = nodes * 36;
    uint4* outbase = (uint4*)g_xw2q;
    for (int idx = threadIdx.x; idx < total; idx += blockDim.x) {
        int node = idx / 36, r = idx - node * 36;
        int g = r >> 2, j = r & 3, p = j >> 1, h = j & 1;
        int k0 = 3 * g + p;
        const unsigned short* s0 = sp + node * 216 + k0 * 8 + 4 * h;   // corner k0, outs 8h..8h+7
        uint2 a = *(const uint2*)s0;
        uint2 b = *(const uint2*)(s0 + 8);                              // corner k0+1
        outbase[((size_t)(blockIdx.x * 32 + node)) * 36 + r] = make_uint4(a.x, a.y, b.x, b.y);
    }
}

// Level-2 edge kernel: per (b1,b2) one aligned 32B sector holds BOTH b0 corners (fp8).
// 8 LDG.128 + 4 sectors of gather per edge; fp32 accumulate; red.v4 scatter.
__global__ void k_edge2(const int* __restrict__ ei, const float* __restrict__ attr,
                        const int* __restrict__ cl1, int E) {
    int e = blockIdx.x * blockDim.x + threadIdx.x;
    if (e >= E) return;
    int src = __ldcs(ei + e), dst = __ldcs(ei + E + e);
    int s2 = __ldg(cl1 + src), d2 = __ldg(cl1 + dst);

    float f[3]; int i0[3];
    spline_coords_ldcs(attr, e, f, i0);

    float msg[16];
#pragma unroll
    for (int o = 0; o < 16; o++) msg[o] = 0.0f;

    const unsigned char* qbase = g_xw2q + (size_t)s2 * 576 + i0[0] * 32;
    float w1a = 1.0f - f[1], w2a = 1.0f - f[2];
    float w0a = 1.0f - f[0], w0b = f[0];
#pragma unroll
    for (int t = 0; t < 4; t++) {
        int b1 = t & 1, b2 = t >> 1;
        float w12 = (b1 ? f[1] : w1a) * (b2 ? f[2] : w2a);
        int g = (i0[1] + b1) + 3 * (i0[2] + b2);
        const uint4* p4 = (const uint4*)(qbase + g * 64);
        uint4 h0 = __ldg(p4);        // outs 0..7 of corners (b0=0 | b0=1)
        uint4 h1 = __ldg(p4 + 1);    // outs 8..15
        float wA = w12 * w0a, wB = w12 * w0b;
        acc_fp8_word(msg + 0,  h0.x, wA);
        acc_fp8_word(msg + 4,  h0.y, wA);
        acc_fp8_word(msg + 0,  h0.z, wB);
        acc_fp8_word(msg + 4,  h0.w, wB);
        acc_fp8_word(msg + 8,  h1.x, wA);
        acc_fp8_word(msg + 12, h1.y, wA);
        acc_fp8_word(msg + 8,  h1.z, wB);
        acc_fp8_word(msg + 12, h1.w, wB);
    }
    float* a = g_s.agg2 + (size_t)d2 * 16;
    red_add_v4(a,      msg[0],  msg[1],  msg[2],  msg[3]);
    red_add_v4(a + 4,  msg[4],  msg[5],  msg[6],  msg[7]);
    red_add_v4(a + 8,  msg[8],  msg[9],  msg[10], msg[11]);
    red_add_v4(a + 12, msg[12], msg[13], msg[14], msg[15]);
}

// Level-2 node kernel: h2 = elu(agg2/cnt2 + x1@root2 + b2); max-pool into cluster2 bins
__global__ void k_node2(const float* __restrict__ root2, const float* __restrict__ b2,
                        const int* __restrict__ cl2, int N1) {
    int n1 = blockIdx.x * blockDim.x + threadIdx.x;
    if (n1 >= N1) return;
    const float4* ar = (const float4*)(g_s.agg2 + (size_t)n1 * 16);
    float ag[16];
#pragma unroll
    for (int q = 0; q < 4; q++) {
        float4 v = ar[q];
        ag[q * 4 + 0] = v.x; ag[q * 4 + 1] = v.y; ag[q * 4 + 2] = v.z; ag[q * 4 + 3] = v.w;
    }
    float inv = 1.0f / fmaxf((float)g_s.cnt2[n1], 1.0f);
    float xv[8];
#pragma unroll
    for (int c = 0; c < 8; c++) xv[c] = g_x1[(size_t)n1 * 8 + c];
    int c2 = cl2[n1];
#pragma unroll
    for (int o = 0; o < 16; o++) {
        float h = ag[o] * inv + __ldg(b2 + o);
#pragma unroll
        for (int c = 0; c < 8; c++) h += xv[c] * __ldg(root2 + c * 16 + o);
        h = elu1(h);
        atomicMax(&g_s.x2enc[(size_t)c2 * 16 + o], fenc(h));
    }
    atomicMax(&g_s.batch2[c2], g_s.batch1[n1]);
}

// Decode x2, per-graph sum/count with shared-memory staging
__global__ void k_pool(int N2) {
    __shared__ float    sg[NB * 16];
    __shared__ unsigned sc[NB];
    if (threadIdx.x < NB * 16) sg[threadIdx.x] = 0.0f;
    if (threadIdx.x < NB)      sc[threadIdx.x] = 0u;
    __syncthreads();
    int n2 = blockIdx.x * blockDim.x + threadIdx.x;
    if (n2 < N2) {
        int b = g_s.batch2[n2];
#pragma unroll
        for (int o = 0; o < 16; o++) {
            float v = fdec0(g_s.x2enc[(size_t)n2 * 16 + o]);
            atomicAdd(&sg[b * 16 + o], v);
        }
        atomicAdd(&sc[b], 1u);
    }
    __syncthreads();
    if (threadIdx.x < NB * 16) atomicAdd(&g_s.gsum[threadIdx.x], sg[threadIdx.x]);
    if (threadIdx.x < NB)      atomicAdd(&g_s.gcnt[threadIdx.x], sc[threadIdx.x]);
}

// Final MLP: g = gsum/cnt; out = elu(elu(g@fc1+b)@fc2+b)
__global__ void k_mlp(const float* __restrict__ fc1_w, const float* __restrict__ fc1_b,
                      const float* __restrict__ fc2_w, const float* __restrict__ fc2_b,
                      float* __restrict__ out) {
    __shared__ float g[NB * 16];
    __shared__ float h[NB * 64];
    for (int idx = threadIdx.x; idx < NB * 16; idx += blockDim.x) {
        int b = idx / 16;
        g[idx] = g_s.gsum[idx] / fmaxf((float)g_s.gcnt[b], 1.0f);
    }
    __syncthreads();
    int j = threadIdx.x;   // 64 threads
    if (j < 64) {
#pragma unroll
        for (int b = 0; b < NB; b++) {
            float acc = __ldg(fc1_b + j);
#pragma unroll
            for (int c = 0; c < 16; c++) acc += g[b * 16 + c] * __ldg(fc1_w + c * 64 + j);
            h[b * 64 + j] = elu1(acc);
        }
    }
    __syncthreads();
    if (j < NB) {
        float acc = __ldg(fc2_b);
#pragma unroll
        for (int q = 0; q < 64; q++) acc += h[j * 64 + q] * __ldg(fc2_w + q);
        out[j] = elu1(acc);
    }
}

// ---------------- launch ----------------
extern "C" void kernel_launch(void* const* d_in, const int* in_sizes, int n_in,
                              void* d_out, int out_size) {
    const float* x      = (const float*)d_in[0];
    const int*   ei     = (const int*)  d_in[1];
    const float* attr   = (const float*)d_in[2];
    const int*   batch  = (const int*)  d_in[3];
    const int*   cl1    = (const int*)  d_in[4];
    const int*   cl2    = (const int*)  d_in[5];
    const float* W1     = (const float*)d_in[6];
    const float* root1  = (const float*)d_in[7];
    const float* b1     = (const float*)d_in[8];
    const float* W2     = (const float*)d_in[9];
    const float* root2  = (const float*)d_in[10];
    const float* b2     = (const float*)d_in[11];
    const float* fc1_w  = (const float*)d_in[12];
    const float* fc1_b  = (const float*)d_in[13];
    const float* fc2_w  = (const float*)d_in[14];
    const float* fc2_b  = (const float*)d_in[15];
    float* out = (float*)d_out;

    int N  = in_sizes[3];          // 80000
    int E  = in_sizes[1] / 2;      // 1280000
    int N1 = in_sizes[5];          // 40000
    int N2 = N1 / 2;               // 20000

    void* scratch_ptr = nullptr;
    cudaGetSymbolAddress(&scratch_ptr, g_s);
    cudaMemsetAsync(scratch_ptr, 0, sizeof(Scratch));

    const int T = 256;
    k_edge1<<<(E + T - 1) / T, T>>>(ei, attr, x, W1, E);
    k_node1<<<(N + T - 1) / T, T>>>(x, root1, b1, batch, cl1, N);
    k_xw2  <<<(N1 + 31) / 32, T>>>(W2, N1);
    k_edge2<<<(E + T - 1) / T, T>>>(ei, attr, cl1, E);
    k_node2<<<(N1 + T - 1) / T, T>>>(root2, b2, cl2, N1);
    k_pool <<<(N2 + T - 1) / T, T>>>(N2);
    k_mlp  <<<1, 64>>>(fc1_w, fc1_b, fc2_w, fc2_b, out);
}

// round 14
// speedup vs baseline: 1.1793x; 1.1793x over previous
#include <cuda_runtime.h>
#include <cuda_fp16.h>
#include <math.h>

// Fixed problem shapes (from setup_inputs)
#define NN   80000
#define NN1  40000
#define NN2  20000
#define NB   16
#define EE   1280000

// ---------------- scratch (device globals; no allocation allowed) ----------------
// Zero-filled per run via one cudaMemsetAsync (empty max-pool encoding = 0x0).
struct Scratch {
    float    agg1[NN * 8];
    unsigned cnt1[NN];
    unsigned x1enc[NN1 * 8];
    int      batch1[NN1];
    float    agg2[NN1 * 16];
    unsigned cnt2[NN1];
    unsigned x2enc[NN2 * 16];
    int      batch2[NN2];
    float    gsum[NB * 16];
    unsigned gcnt[NB];
    unsigned cntsrc[NN1];      // level-2 per-src2 edge histogram (for counting sort)
};
__device__ __align__(16) Scratch g_s;
__device__ __align__(16) float    g_x1[NN1 * 8];               // fully written by k_xw2
__device__ __align__(32) __half   g_xw2h[(size_t)NN1 * 432];   // [N1][27][16] fp16 = 34.5 MB
__device__            unsigned    g_off[NN1];                  // bin cursors (fully written by k_scan)
__device__ __align__(16) uint4    g_srtA[EE];                  // {s2, d2|i0<<16, f0, f1}
__device__            float       g_srtF2[EE];

// ---------------- helpers ----------------
__device__ __forceinline__ float elu1(float v) { return v > 0.0f ? v : expm1f(v); }

// order-preserving float <-> uint encoding for atomicMax on floats (0x0 = empty -> 0.0)
__device__ __forceinline__ unsigned fenc(float f) {
    unsigned u = __float_as_uint(f);
    return (u & 0x80000000u) ? ~u : (u | 0x80000000u);
}
__device__ __forceinline__ float fdec0(unsigned u) {
    if (u == 0u) return 0.0f;
    return (u & 0x80000000u) ? __uint_as_float(u & 0x7fffffffu) : __uint_as_float(~u);
}

__device__ __forceinline__ __half2 u2h2(unsigned u) {
    return *reinterpret_cast<__half2*>(&u);
}

__device__ __forceinline__ void red_add_v4(float* addr, float a, float b, float c, float d) {
    asm volatile("red.global.add.v4.f32 [%0], {%1, %2, %3, %4};"
                 :: "l"(addr), "f"(a), "f"(b), "f"(c), "f"(d) : "memory");
}

// B-spline (degree 1, K=3) fractional parts + base indices from pseudo coords
__device__ __forceinline__ void spline_coords_ldcs(const float* __restrict__ attr, int e,
                                                   float f[3], int i0[3]) {
#pragma unroll
    for (int d = 0; d < 3; d++) {
        float v  = __ldcs(attr + 3 * (size_t)e + d) * 2.0f;   // pseudo * (K-1)
        float fl = floorf(v);
        fl = fminf(fmaxf(fl, 0.0f), 1.0f);                    // clip to [0, K-2] -> i0 in {0,1}
        i0[d] = (int)fl;
        f[d]  = v - fl;
    }
}

__device__ __forceinline__ void acc_h2(float& a, float& b, unsigned u, float w) {
    __half2 h = u2h2(u);
    float2 fv = __half22float2(h);
    a += w * fv.x; b += w * fv.y;
}

// ---------------- kernels ----------------
// Level-1 edge kernel + src2 histogram for the level-2 counting sort
__global__ void k_edge1(const int* __restrict__ ei, const float* __restrict__ attr,
                        const float* __restrict__ x, const float* __restrict__ W1,
                        const int* __restrict__ cl1, int E) {
    __shared__ float Ws[27 * 17];
    for (int j = threadIdx.x; j < 432; j += blockDim.x)
        Ws[(j >> 4) * 17 + (j & 15)] = W1[j];
    __syncthreads();

    int e = blockIdx.x * blockDim.x + threadIdx.x;
    if (e >= E) return;
    int src = __ldcs(ei + e), dst = __ldcs(ei + E + e);

    float f[3]; int i0[3];
    spline_coords_ldcs(attr, e, f, i0);

    float2 xv = *(const float2*)(x + 2 * (size_t)src);

    float msg[8];
#pragma unroll
    for (int o = 0; o < 8; o++) msg[o] = 0.0f;

#pragma unroll
    for (int s = 0; s < 8; s++) {
        int b0 = s & 1, b1 = (s >> 1) & 1, b2 = (s >> 2) & 1;
        float w = (b0 ? f[0] : 1.0f - f[0]) * (b1 ? f[1] : 1.0f - f[1]) * (b2 ? f[2] : 1.0f - f[2]);
        int k = (i0[0] + b0) + 3 * (i0[1] + b1) + 9 * (i0[2] + b2);
        const float* wp = Ws + k * 17;
        float wx = w * xv.x, wy = w * xv.y;
#pragma unroll
        for (int o = 0; o < 8; o++) msg[o] += wx * wp[o] + wy * wp[8 + o];
    }
    float* a = g_s.agg1 + (size_t)dst * 8;
    red_add_v4(a,     msg[0], msg[1], msg[2], msg[3]);
    red_add_v4(a + 4, msg[4], msg[5], msg[6], msg[7]);
    atomicAdd(&g_s.cnt1[dst], 1u);
    atomicAdd(&g_s.cntsrc[__ldg(cl1 + src)], 1u);   // histogram for counting sort
}

// Exclusive scan of cntsrc[N1] -> g_off (single block, 1024 threads x 40 elems)
__global__ void k_scan(int N1) {
    __shared__ unsigned part[1024];
    int t = threadIdx.x;
    const int PER = 40;
    int start = t * PER;
    unsigned sum = 0;
    for (int i = 0; i < PER; i++) {
        int idx = start + i;
        if (idx < N1) sum += g_s.cntsrc[idx];
    }
    part[t] = sum;
    __syncthreads();
    for (int d = 1; d < 1024; d <<= 1) {
        unsigned v = (t >= d) ? part[t - d] : 0u;
        __syncthreads();
        part[t] += v;
        __syncthreads();
    }
    unsigned run = part[t] - sum;   // exclusive
    for (int i = 0; i < PER; i++) {
        int idx = start + i;
        if (idx < N1) {
            g_off[idx] = run;
            run += g_s.cntsrc[idx];
        }
    }
}

// Scatter edges into src2-sorted order (fp32 basis, no precision loss)
__global__ void k_scatter(const int* __restrict__ ei, const float* __restrict__ attr,
                          const int* __restrict__ cl1, int E) {
    int e = blockIdx.x * blockDim.x + threadIdx.x;
    if (e >= E) return;
    int src = __ldcs(ei + e), dst = __ldcs(ei + E + e);
    int s2 = __ldg(cl1 + src), d2 = __ldg(cl1 + dst);

    float f[3]; int i0[3];
    spline_coords_ldcs(attr, e, f, i0);

    unsigned pos = atomicAdd(&g_off[s2], 1u);
    unsigned pack = (unsigned)d2 | ((unsigned)(i0[0] | (i0[1] << 1) | (i0[2] << 2)) << 16);
    g_srtA[pos]  = make_uint4((unsigned)s2, pack, __float_as_uint(f[0]), __float_as_uint(f[1]));
    g_srtF2[pos] = f[2];
}

// Level-1 node kernel: h = elu(agg/cnt + x@root1 + b1); max-pool into cluster1 bins.
// Also aggregates cnt1 -> cnt2.
__global__ void k_node1(const float* __restrict__ x, const float* __restrict__ root1,
                        const float* __restrict__ b1, const int* __restrict__ batch,
                        const int* __restrict__ cl1, int N) {
    int n = blockIdx.x * blockDim.x + threadIdx.x;
    if (n >= N) return;
    const float4* ar = (const float4*)(g_s.agg1 + (size_t)n * 8);
    float4 a0 = ar[0], a1 = ar[1];
    float ag[8] = {a0.x, a0.y, a0.z, a0.w, a1.x, a1.y, a1.z, a1.w};
    unsigned c1 = g_s.cnt1[n];
    float inv = 1.0f / fmaxf((float)c1, 1.0f);
    float2 xv = *(const float2*)(x + 2 * (size_t)n);
    int c = cl1[n];
#pragma unroll
    for (int o = 0; o < 8; o++) {
        float h = ag[o] * inv + xv.x * __ldg(root1 + o) + xv.y * __ldg(root1 + 8 + o) + __ldg(b1 + o);
        h = elu1(h);
        atomicMax(&g_s.x1enc[(size_t)c * 8 + o], fenc(h));
    }
    atomicMax(&g_s.batch1[c], batch[n]);
    if (c1) atomicAdd(&g_s.cnt2[c], c1);
}

// Decode x1 + precompute xW2 in fp16: xw2[n1][k][o] = sum_c x1[n1][c] * W2[k][c][o]
__global__ void k_xw2(const float* __restrict__ W2, int N1) {
    __shared__ float Ws[3456];
    for (int j = threadIdx.x; j < 3456; j += blockDim.x) Ws[j] = W2[j];
    __syncthreads();
    int n1 = blockIdx.x * 32 + (threadIdx.x >> 3);
    int q  = threadIdx.x & 7;
    if (n1 >= N1) return;
    float xv[8];
#pragma unroll
    for (int c = 0; c < 8; c++)
        xv[c] = fdec0(g_s.x1enc[(size_t)n1 * 8 + c]);
    if (q < 4)
        *(float2*)(g_x1 + (size_t)n1 * 8 + 2 * q) = make_float2(xv[2 * q], xv[2 * q + 1]);

    __half2* outp = (__half2*)(g_xw2h + (size_t)n1 * 432) + q;
    int o0 = 2 * q;
#pragma unroll
    for (int k = 0; k < 27; k++) {
        float acc0 = 0.0f, acc1 = 0.0f;
#pragma unroll
        for (int c = 0; c < 8; c++) {
            acc0 += xv[c] * Ws[k * 128 + c * 16 + o0];
            acc1 += xv[c] * Ws[k * 128 + c * 16 + o0 + 1];
        }
        outp[k * 8] = __floats2half2_rn(acc0, acc1);
    }
}

// Level-2 edge kernel on src2-SORTED records: adjacent lanes share xw2 rows ->
// L1 line reuse on the gather. fp32 accumulate; red.v4 scatter to agg2[dst2].
__global__ void k_edge2(int E) {
    int e = blockIdx.x * blockDim.x + threadIdx.x;
    if (e >= E) return;
    uint4 rec = g_srtA[e];           // coalesced
    float f2  = g_srtF2[e];
    int s2 = (int)rec.x;
    int d2 = (int)(rec.y & 0xFFFFu);
    int ip = (int)(rec.y >> 16);
    int i00 = ip & 1, i01 = (ip >> 1) & 1, i02 = (ip >> 2) & 1;
    float f0 = __uint_as_float(rec.z), f1 = __uint_as_float(rec.w);

    float msg[16];
#pragma unroll
    for (int o = 0; o < 16; o++) msg[o] = 0.0f;

    const __half* basep = g_xw2h + (size_t)s2 * 432;
    float w1a = 1.0f - f1, w2a = 1.0f - f2;
    float w0a = 1.0f - f0, w0b = f0;
#pragma unroll
    for (int t = 0; t < 4; t++) {
        int b1 = t & 1, b2 = t >> 1;
        float w12 = (b1 ? f1 : w1a) * (b2 ? f2 : w2a);
        int kb = i00 + 3 * (i01 + b1) + 9 * (i02 + b2);
        const uint4* p = (const uint4*)(basep + kb * 16);   // 64B: corner b0=0 then b0=1
        uint4 v0 = __ldg(p);
        uint4 v1 = __ldg(p + 1);
        uint4 v2 = __ldg(p + 2);
        uint4 v3 = __ldg(p + 3);
        float wA = w12 * w0a, wB = w12 * w0b;
        acc_h2(msg[0],  msg[1],  v0.x, wA);
        acc_h2(msg[2],  msg[3],  v0.y, wA);
        acc_h2(msg[4],  msg[5],  v0.z, wA);
        acc_h2(msg[6],  msg[7],  v0.w, wA);
        acc_h2(msg[8],  msg[9],  v1.x, wA);
        acc_h2(msg[10], msg[11], v1.y, wA);
        acc_h2(msg[12], msg[13], v1.z, wA);
        acc_h2(msg[14], msg[15], v1.w, wA);
        acc_h2(msg[0],  msg[1],  v2.x, wB);
        acc_h2(msg[2],  msg[3],  v2.y, wB);
        acc_h2(msg[4],  msg[5],  v2.z, wB);
        acc_h2(msg[6],  msg[7],  v2.w, wB);
        acc_h2(msg[8],  msg[9],  v3.x, wB);
        acc_h2(msg[10], msg[11], v3.y, wB);
        acc_h2(msg[12], msg[13], v3.z, wB);
        acc_h2(msg[14], msg[15], v3.w, wB);
    }
    float* a = g_s.agg2 + (size_t)d2 * 16;
    red_add_v4(a,      msg[0],  msg[1],  msg[2],  msg[3]);
    red_add_v4(a + 4,  msg[4],  msg[5],  msg[6],  msg[7]);
    red_add_v4(a + 8,  msg[8],  msg[9],  msg[10], msg[11]);
    red_add_v4(a + 12, msg[12], msg[13], msg[14], msg[15]);
}

// Level-2 node kernel: h2 = elu(agg2/cnt2 + x1@root2 + b2); max-pool into cluster2 bins
__global__ void k_node2(const float* __restrict__ root2, const float* __restrict__ b2,
                        const int* __restrict__ cl2, int N1) {
    int n1 = blockIdx.x * blockDim.x + threadIdx.x;
    if (n1 >= N1) return;
    const float4* ar = (const float4*)(g_s.agg2 + (size_t)n1 * 16);
    float ag[16];
#pragma unroll
    for (int q = 0; q < 4; q++) {
        float4 v = ar[q];
        ag[q * 4 + 0] = v.x; ag[q * 4 + 1] = v.y; ag[q * 4 + 2] = v.z; ag[q * 4 + 3] = v.w;
    }
    float inv = 1.0f / fmaxf((float)g_s.cnt2[n1], 1.0f);
    float xv[8];
#pragma unroll
    for (int c = 0; c < 8; c++) xv[c] = g_x1[(size_t)n1 * 8 + c];
    int c2 = cl2[n1];
#pragma unroll
    for (int o = 0; o < 16; o++) {
        float h = ag[o] * inv + __ldg(b2 + o);
#pragma unroll
        for (int c = 0; c < 8; c++) h += xv[c] * __ldg(root2 + c * 16 + o);
        h = elu1(h);
        atomicMax(&g_s.x2enc[(size_t)c2 * 16 + o], fenc(h));
    }
    atomicMax(&g_s.batch2[c2], g_s.batch1[n1]);
}

// Decode x2, per-graph sum/count with shared-memory staging
__global__ void k_pool(int N2) {
    __shared__ float    sg[NB * 16];
    __shared__ unsigned sc[NB];
    if (threadIdx.x < NB * 16) sg[threadIdx.x] = 0.0f;
    if (threadIdx.x < NB)      sc[threadIdx.x] = 0u;
    __syncthreads();
    int n2 = blockIdx.x * blockDim.x + threadIdx.x;
    if (n2 < N2) {
        int b = g_s.batch2[n2];
#pragma unroll
        for (int o = 0; o < 16; o++) {
            float v = fdec0(g_s.x2enc[(size_t)n2 * 16 + o]);
            atomicAdd(&sg[b * 16 + o], v);
        }
        atomicAdd(&sc[b], 1u);
    }
    __syncthreads();
    if (threadIdx.x < NB * 16) atomicAdd(&g_s.gsum[threadIdx.x], sg[threadIdx.x]);
    if (threadIdx.x < NB)      atomicAdd(&g_s.gcnt[threadIdx.x], sc[threadIdx.x]);
}

// Final MLP
__global__ void k_mlp(const float* __restrict__ fc1_w, const float* __restrict__ fc1_b,
                      const float* __restrict__ fc2_w, const float* __restrict__ fc2_b,
                      float* __restrict__ out) {
    __shared__ float g[NB * 16];
    __shared__ float h[NB * 64];
    for (int idx = threadIdx.x; idx < NB * 16; idx += blockDim.x) {
        int b = idx / 16;
        g[idx] = g_s.gsum[idx] / fmaxf((float)g_s.gcnt[b], 1.0f);
    }
    __syncthreads();
    int j = threadIdx.x;   // 64 threads
    if (j < 64) {
#pragma unroll
        for (int b = 0; b < NB; b++) {
            float acc = __ldg(fc1_b + j);
#pragma unroll
            for (int c = 0; c < 16; c++) acc += g[b * 16 + c] * __ldg(fc1_w + c * 64 + j);
            h[b * 64 + j] = elu1(acc);
        }
    }
    __syncthreads();
    if (j < NB) {
        float acc = __ldg(fc2_b);
#pragma unroll
        for (int q = 0; q < 64; q++) acc += h[j * 64 + q] * __ldg(fc2_w + q);
        out[j] = elu1(acc);
    }
}

// ---------------- launch ----------------
extern "C" void kernel_launch(void* const* d_in, const int* in_sizes, int n_in,
                              void* d_out, int out_size) {
    const float* x      = (const float*)d_in[0];
    const int*   ei     = (const int*)  d_in[1];
    const float* attr   = (const float*)d_in[2];
    const int*   batch  = (const int*)  d_in[3];
    const int*   cl1    = (const int*)  d_in[4];
    const int*   cl2    = (const int*)  d_in[5];
    const float* W1     = (const float*)d_in[6];
    const float* root1  = (const float*)d_in[7];
    const float* b1     = (const float*)d_in[8];
    const float* W2     = (const float*)d_in[9];
    const float* root2  = (const float*)d_in[10];
    const float* b2     = (const float*)d_in[11];
    const float* fc1_w  = (const float*)d_in[12];
    const float* fc1_b  = (const float*)d_in[13];
    const float* fc2_w  = (const float*)d_in[14];
    const float* fc2_b  = (const float*)d_in[15];
    float* out = (float*)d_out;

    int N  = in_sizes[3];          // 80000
    int E  = in_sizes[1] / 2;      // 1280000
    int N1 = in_sizes[5];          // 40000
    int N2 = N1 / 2;               // 20000

    void* scratch_ptr = nullptr;
    cudaGetSymbolAddress(&scratch_ptr, g_s);
    cudaMemsetAsync(scratch_ptr, 0, sizeof(Scratch));

    const int T = 256;
    k_edge1  <<<(E + T - 1) / T, T>>>(ei, attr, x, W1, cl1, E);
    k_scan   <<<1, 1024>>>(N1);
    k_scatter<<<(E + T - 1) / T, T>>>(ei, attr, cl1, E);
    k_node1  <<<(N + T - 1) / T, T>>>(x, root1, b1, batch, cl1, N);
    k_xw2    <<<(N1 + 31) / 32, T>>>(W2, N1);
    k_edge2  <<<(E + T - 1) / T, T>>>(E);
    k_node2  <<<(N1 + T - 1) / T, T>>>(root2, b2, cl2, N1);
    k_pool   <<<(N2 + T - 1) / T, T>>>(N2);
    k_mlp    <<<1, 64>>>(fc1_w, fc1_b, fc2_w, fc2_b, out);
}

// round 15
// speedup vs baseline: 1.6307x; 1.3828x over previous
#include <cuda_runtime.h>
#include <cuda_fp16.h>
#include <math.h>

// Fixed problem shapes (from setup_inputs)
#define NN   80000
#define NN1  40000
#define NN2  20000
#define NB   16

// ---------------- scratch (device globals; no allocation allowed) ----------------
// Zero-filled per run via one cudaMemsetAsync (empty max-pool encoding = 0x0).
struct Scratch {
    float    agg1[NN * 8];
    unsigned cnt1[NN];
    unsigned x1enc[NN1 * 8];
    int      batch1[NN1];
    float    agg2[NN1 * 16];
    unsigned cnt2[NN1];
    unsigned x2enc[NN2 * 16];
    int      batch2[NN2];
    float    gsum[NB * 16];
    unsigned gcnt[NB];
};
__device__ __align__(16) Scratch g_s;
__device__ __align__(16) float    g_x1[NN1 * 8];               // fully written by k_xw2
__device__ __align__(32) __half   g_xw2h[(size_t)NN1 * 432];   // [N1][27][16] fp16 = 34.5 MB

// ---------------- helpers ----------------
__device__ __forceinline__ float elu1(float v) { return v > 0.0f ? v : expm1f(v); }

// order-preserving float <-> uint encoding for atomicMax on floats (0x0 = empty -> 0.0)
__device__ __forceinline__ unsigned fenc(float f) {
    unsigned u = __float_as_uint(f);
    return (u & 0x80000000u) ? ~u : (u | 0x80000000u);
}
__device__ __forceinline__ float fdec0(unsigned u) {
    if (u == 0u) return 0.0f;
    return (u & 0x80000000u) ? __uint_as_float(u & 0x7fffffffu) : __uint_as_float(~u);
}

__device__ __forceinline__ __half2 u2h2(unsigned u) {
    return *reinterpret_cast<__half2*>(&u);
}

__device__ __forceinline__ void red_add_v4(float* addr, float a, float b, float c, float d) {
    asm volatile("red.global.add.v4.f32 [%0], {%1, %2, %3, %4};"
                 :: "l"(addr), "f"(a), "f"(b), "f"(c), "f"(d) : "memory");
}

// B-spline (degree 1, K=3) fractional parts + base indices from pseudo coords
__device__ __forceinline__ void spline_coords_ldcs(const float* __restrict__ attr, int e,
                                                   float f[3], int i0[3]) {
#pragma unroll
    for (int d = 0; d < 3; d++) {
        float v  = __ldcs(attr + 3 * (size_t)e + d) * 2.0f;   // pseudo * (K-1)
        float fl = floorf(v);
        fl = fminf(fmaxf(fl, 0.0f), 1.0f);                    // clip to [0, K-2]
        i0[d] = (int)fl;
        f[d]  = v - fl;
    }
}

__device__ __forceinline__ void acc_h2(float& a, float& b, unsigned u, float w) {
    __half2 h = u2h2(u);
    float2 fv = __half22float2(h);
    a += w * fv.x; b += w * fv.y;
}

// ---------------- kernels ----------------
// Level-1 edge kernel: msg[o] = sum_s basis_s * (x[src] . W1[k_s][:,o]); scatter-add to agg1[dst]
__global__ void k_edge1(const int* __restrict__ ei, const float* __restrict__ attr,
                        const float* __restrict__ x, const float* __restrict__ W1, int E) {
    __shared__ float Ws[27 * 17];
    for (int j = threadIdx.x; j < 432; j += blockDim.x)
        Ws[(j >> 4) * 17 + (j & 15)] = W1[j];
    __syncthreads();

    int e = blockIdx.x * blockDim.x + threadIdx.x;
    if (e >= E) return;
    int src = __ldcs(ei + e), dst = __ldcs(ei + E + e);

    float f[3]; int i0[3];
    spline_coords_ldcs(attr, e, f, i0);

    float2 xv = *(const float2*)(x + 2 * (size_t)src);

    float msg[8];
#pragma unroll
    for (int o = 0; o < 8; o++) msg[o] = 0.0f;

#pragma unroll
    for (int s = 0; s < 8; s++) {
        int b0 = s & 1, b1 = (s >> 1) & 1, b2 = (s >> 2) & 1;
        float w = (b0 ? f[0] : 1.0f - f[0]) * (b1 ? f[1] : 1.0f - f[1]) * (b2 ? f[2] : 1.0f - f[2]);
        int k = (i0[0] + b0) + 3 * (i0[1] + b1) + 9 * (i0[2] + b2);
        const float* wp = Ws + k * 17;
        float wx = w * xv.x, wy = w * xv.y;
#pragma unroll
        for (int o = 0; o < 8; o++) msg[o] += wx * wp[o] + wy * wp[8 + o];
    }
    float* a = g_s.agg1 + (size_t)dst * 8;
    red_add_v4(a,     msg[0], msg[1], msg[2], msg[3]);
    red_add_v4(a + 4, msg[4], msg[5], msg[6], msg[7]);
    atomicAdd(&g_s.cnt1[dst], 1u);
}

// Level-1 node kernel: h = elu(agg/cnt + x@root1 + b1); max-pool into cluster1 bins.
// Also aggregates cnt1 -> cnt2.
__global__ void k_node1(const float* __restrict__ x, const float* __restrict__ root1,
                        const float* __restrict__ b1, const int* __restrict__ batch,
                        const int* __restrict__ cl1, int N) {
    int n = blockIdx.x * blockDim.x + threadIdx.x;
    if (n >= N) return;
    const float4* ar = (const float4*)(g_s.agg1 + (size_t)n * 8);
    float4 a0 = ar[0], a1 = ar[1];
    float ag[8] = {a0.x, a0.y, a0.z, a0.w, a1.x, a1.y, a1.z, a1.w};
    unsigned c1 = g_s.cnt1[n];
    float inv = 1.0f / fmaxf((float)c1, 1.0f);
    float2 xv = *(const float2*)(x + 2 * (size_t)n);
    int c = cl1[n];
#pragma unroll
    for (int o = 0; o < 8; o++) {
        float h = ag[o] * inv + xv.x * __ldg(root1 + o) + xv.y * __ldg(root1 + 8 + o) + __ldg(b1 + o);
        h = elu1(h);
        atomicMax(&g_s.x1enc[(size_t)c * 8 + o], fenc(h));
    }
    atomicMax(&g_s.batch1[c], batch[n]);
    if (c1) atomicAdd(&g_s.cnt2[c], c1);
}

// Decode x1 + precompute xW2 in fp16: xw2[n1][k][o] = sum_c x1[n1][c] * W2[k][c][o]
__global__ void k_xw2(const float* __restrict__ W2, int N1) {
    __shared__ float Ws[3456];
    for (int j = threadIdx.x; j < 3456; j += blockDim.x) Ws[j] = W2[j];
    __syncthreads();
    int n1 = blockIdx.x * 32 + (threadIdx.x >> 3);
    int q  = threadIdx.x & 7;
    if (n1 >= N1) return;
    float xv[8];
#pragma unroll
    for (int c = 0; c < 8; c++)
        xv[c] = fdec0(g_s.x1enc[(size_t)n1 * 8 + c]);
    if (q < 4)
        *(float2*)(g_x1 + (size_t)n1 * 8 + 2 * q) = make_float2(xv[2 * q], xv[2 * q + 1]);

    __half2* outp = (__half2*)(g_xw2h + (size_t)n1 * 432) + q;
    int o0 = 2 * q;
#pragma unroll
    for (int k = 0; k < 27; k++) {
        float acc0 = 0.0f, acc1 = 0.0f;
#pragma unroll
        for (int c = 0; c < 8; c++) {
            acc0 += xv[c] * Ws[k * 128 + c * 16 + o0];
            acc1 += xv[c] * Ws[k * 128 + c * 16 + o0 + 1];
        }
        outp[k * 8] = __floats2half2_rn(acc0, acc1);
    }
}

// Level-2 edge kernel: 2 THREADS PER EDGE, split by output half.
// Lane 2t: outputs 0-7 of edge; lane 2t+1: outputs 8-15.
// Each thread: 8 LDG.128 (16B), 8 fp32 accumulators, 2 red.v4.
// Same total lines/REDG lanes as 1-thread version; half the dependent chain,
// double the warp-level parallelism.
__global__ void k_edge2(const int* __restrict__ ei, const float* __restrict__ attr,
                        const int* __restrict__ cl1, int E) {
    int tid = blockIdx.x * blockDim.x + threadIdx.x;
    int e = tid >> 1;
    int half = tid & 1;
    if (e >= E) return;
    int src = __ldcs(ei + e), dst = __ldcs(ei + E + e);
    int s2 = __ldg(cl1 + src), d2 = __ldg(cl1 + dst);

    float f[3]; int i0[3];
    spline_coords_ldcs(attr, e, f, i0);

    float msg[8];
#pragma unroll
    for (int o = 0; o < 8; o++) msg[o] = 0.0f;

    // per-corner half-row: bytes k*32 + half*16
    const unsigned char* basep = (const unsigned char*)g_xw2h + (size_t)s2 * 864 + half * 16;
    float w1a = 1.0f - f[1], w2a = 1.0f - f[2];
    float w0a = 1.0f - f[0], w0b = f[0];
#pragma unroll
    for (int t = 0; t < 4; t++) {
        int b1 = t & 1, b2 = t >> 1;
        float w12 = (b1 ? f[1] : w1a) * (b2 ? f[2] : w2a);
        int kb = i0[0] + 3 * (i0[1] + b1) + 9 * (i0[2] + b2);
        const uint4* pA = (const uint4*)(basep + (size_t)kb * 32);        // corner b0=0
        const uint4* pB = (const uint4*)(basep + (size_t)(kb + 1) * 32);  // corner b0=1
        uint4 vA = __ldg(pA);
        uint4 vB = __ldg(pB);
        float wA = w12 * w0a, wB = w12 * w0b;
        acc_h2(msg[0], msg[1], vA.x, wA);
        acc_h2(msg[2], msg[3], vA.y, wA);
        acc_h2(msg[4], msg[5], vA.z, wA);
        acc_h2(msg[6], msg[7], vA.w, wA);
        acc_h2(msg[0], msg[1], vB.x, wB);
        acc_h2(msg[2], msg[3], vB.y, wB);
        acc_h2(msg[4], msg[5], vB.z, wB);
        acc_h2(msg[6], msg[7], vB.w, wB);
    }
    float* a = g_s.agg2 + (size_t)d2 * 16 + half * 8;
    red_add_v4(a,     msg[0], msg[1], msg[2], msg[3]);
    red_add_v4(a + 4, msg[4], msg[5], msg[6], msg[7]);
}

// Level-2 node kernel: h2 = elu(agg2/cnt2 + x1@root2 + b2); max-pool into cluster2 bins
__global__ void k_node2(const float* __restrict__ root2, const float* __restrict__ b2,
                        const int* __restrict__ cl2, int N1) {
    int n1 = blockIdx.x * blockDim.x + threadIdx.x;
    if (n1 >= N1) return;
    const float4* ar = (const float4*)(g_s.agg2 + (size_t)n1 * 16);
    float ag[16];
#pragma unroll
    for (int q = 0; q < 4; q++) {
        float4 v = ar[q];
        ag[q * 4 + 0] = v.x; ag[q * 4 + 1] = v.y; ag[q * 4 + 2] = v.z; ag[q * 4 + 3] = v.w;
    }
    float inv = 1.0f / fmaxf((float)g_s.cnt2[n1], 1.0f);
    float xv[8];
#pragma unroll
    for (int c = 0; c < 8; c++) xv[c] = g_x1[(size_t)n1 * 8 + c];
    int c2 = cl2[n1];
#pragma unroll
    for (int o = 0; o < 16; o++) {
        float h = ag[o] * inv + __ldg(b2 + o);
#pragma unroll
        for (int c = 0; c < 8; c++) h += xv[c] * __ldg(root2 + c * 16 + o);
        h = elu1(h);
        atomicMax(&g_s.x2enc[(size_t)c2 * 16 + o], fenc(h));
    }
    atomicMax(&g_s.batch2[c2], g_s.batch1[n1]);
}

// Decode x2, per-graph sum/count with shared-memory staging
__global__ void k_pool(int N2) {
    __shared__ float    sg[NB * 16];
    __shared__ unsigned sc[NB];
    if (threadIdx.x < NB * 16) sg[threadIdx.x] = 0.0f;
    if (threadIdx.x < NB)      sc[threadIdx.x] = 0u;
    __syncthreads();
    int n2 = blockIdx.x * blockDim.x + threadIdx.x;
    if (n2 < N2) {
        int b = g_s.batch2[n2];
#pragma unroll
        for (int o = 0; o < 16; o++) {
            float v = fdec0(g_s.x2enc[(size_t)n2 * 16 + o]);
            atomicAdd(&sg[b * 16 + o], v);
        }
        atomicAdd(&sc[b], 1u);
    }
    __syncthreads();
    if (threadIdx.x < NB * 16) atomicAdd(&g_s.gsum[threadIdx.x], sg[threadIdx.x]);
    if (threadIdx.x < NB)      atomicAdd(&g_s.gcnt[threadIdx.x], sc[threadIdx.x]);
}

// Final MLP
__global__ void k_mlp(const float* __restrict__ fc1_w, const float* __restrict__ fc1_b,
                      const float* __restrict__ fc2_w, const float* __restrict__ fc2_b,
                      float* __restrict__ out) {
    __shared__ float g[NB * 16];
    __shared__ float h[NB * 64];
    for (int idx = threadIdx.x; idx < NB * 16; idx += blockDim.x) {
        int b = idx / 16;
        g[idx] = g_s.gsum[idx] / fmaxf((float)g_s.gcnt[b], 1.0f);
    }
    __syncthreads();
    int j = threadIdx.x;   // 64 threads
    if (j < 64) {
#pragma unroll
        for (int b = 0; b < NB; b++) {
            float acc = __ldg(fc1_b + j);
#pragma unroll
            for (int c = 0; c < 16; c++) acc += g[b * 16 + c] * __ldg(fc1_w + c * 64 + j);
            h[b * 64 + j] = elu1(acc);
        }
    }
    __syncthreads();
    if (j < NB) {
        float acc = __ldg(fc2_b);
#pragma unroll
        for (int q = 0; q < 64; q++) acc += h[j * 64 + q] * __ldg(fc2_w + q);
        out[j] = elu1(acc);
    }
}

// ---------------- launch ----------------
extern "C" void kernel_launch(void* const* d_in, const int* in_sizes, int n_in,
                              void* d_out, int out_size) {
    const float* x      = (const float*)d_in[0];
    const int*   ei     = (const int*)  d_in[1];
    const float* attr   = (const float*)d_in[2];
    const int*   batch  = (const int*)  d_in[3];
    const int*   cl1    = (const int*)  d_in[4];
    const int*   cl2    = (const int*)  d_in[5];
    const float* W1     = (const float*)d_in[6];
    const float* root1  = (const float*)d_in[7];
    const float* b1     = (const float*)d_in[8];
    const float* W2     = (const float*)d_in[9];
    const float* root2  = (const float*)d_in[10];
    const float* b2     = (const float*)d_in[11];
    const float* fc1_w  = (const float*)d_in[12];
    const float* fc1_b  = (const float*)d_in[13];
    const float* fc2_w  = (const float*)d_in[14];
    const float* fc2_b  = (const float*)d_in[15];
    float* out = (float*)d_out;

    int N  = in_sizes[3];          // 80000
    int E  = in_sizes[1] / 2;      // 1280000
    int N1 = in_sizes[5];          // 40000
    int N2 = N1 / 2;               // 20000

    void* scratch_ptr = nullptr;
    cudaGetSymbolAddress(&scratch_ptr, g_s);
    cudaMemsetAsync(scratch_ptr, 0, sizeof(Scratch));

    const int T = 256;
    k_edge1<<<(E + T - 1) / T, T>>>(ei, attr, x, W1, E);
    k_node1<<<(N + T - 1) / T, T>>>(x, root1, b1, batch, cl1, N);
    k_xw2  <<<(N1 + 31) / 32, T>>>(W2, N1);
    k_edge2<<<(2 * E + T - 1) / T, T>>>(ei, attr, cl1, E);
    k_node2<<<(N1 + T - 1) / T, T>>>(root2, b2, cl2, N1);
    k_pool <<<(N2 + T - 1) / T, T>>>(N2);
    k_mlp  <<<1, 64>>>(fc1_w, fc1_b, fc2_w, fc2_b, out);
}

// round 16
// speedup vs baseline: 1.6740x; 1.0265x over previous
#include <cuda_runtime.h>
#include <cuda_fp16.h>
#include <math.h>

// Fixed problem shapes (from setup_inputs)
#define NN   80000
#define NN1  40000
#define NN2  20000
#define NB   16

// ---------------- scratch (device globals; no allocation allowed) ----------------
// Zero-filled per run via one cudaMemsetAsync (empty max-pool encoding = 0x0).
struct Scratch {
    float    agg1[NN * 8];
    unsigned cnt1[NN];
    unsigned x1enc[NN1 * 8];
    int      batch1[NN1];
    float    agg2[NN1 * 16];
    unsigned cnt2[NN1];
    unsigned x2enc[NN2 * 16];
    int      batch2[NN2];
    float    gsum[NB * 16];
    unsigned gcnt[NB];
};
__device__ __align__(16) Scratch g_s;
__device__ __align__(16) float    g_x1[NN1 * 8];               // fully written by k_xw2
__device__ __align__(32) __half   g_xw2h[(size_t)NN1 * 432];   // [N1][27][16] fp16 = 34.5 MB

// ---------------- helpers ----------------
__device__ __forceinline__ float elu1(float v) { return v > 0.0f ? v : expm1f(v); }

// order-preserving float <-> uint encoding for atomicMax on floats (0x0 = empty -> 0.0)
__device__ __forceinline__ unsigned fenc(float f) {
    unsigned u = __float_as_uint(f);
    return (u & 0x80000000u) ? ~u : (u | 0x80000000u);
}
__device__ __forceinline__ float fdec0(unsigned u) {
    if (u == 0u) return 0.0f;
    return (u & 0x80000000u) ? __uint_as_float(u & 0x7fffffffu) : __uint_as_float(~u);
}

__device__ __forceinline__ __half2 u2h2(unsigned u) {
    return *reinterpret_cast<__half2*>(&u);
}

__device__ __forceinline__ void red_add_v4(float* addr, float a, float b, float c, float d) {
    asm volatile("red.global.add.v4.f32 [%0], {%1, %2, %3, %4};"
                 :: "l"(addr), "f"(a), "f"(b), "f"(c), "f"(d) : "memory");
}

// B-spline (degree 1, K=3) fractional parts + base indices from pseudo coords
__device__ __forceinline__ void spline_coords_ldcs(const float* __restrict__ attr, int e,
                                                   float f[3], int i0[3]) {
#pragma unroll
    for (int d = 0; d < 3; d++) {
        float v  = __ldcs(attr + 3 * (size_t)e + d) * 2.0f;   // pseudo * (K-1)
        float fl = floorf(v);
        fl = fminf(fmaxf(fl, 0.0f), 1.0f);                    // clip to [0, K-2]
        i0[d] = (int)fl;
        f[d]  = v - fl;
    }
}

__device__ __forceinline__ void acc_h2(float& a, float& b, unsigned u, float w) {
    __half2 h = u2h2(u);
    float2 fv = __half22float2(h);
    a += w * fv.x; b += w * fv.y;
}

// ---------------- kernels ----------------
// Level-1 edge kernel: msg[o] = sum_s basis_s * (x[src] . W1[k_s][:,o]); scatter-add to agg1[dst]
__global__ void k_edge1(const int* __restrict__ ei, const float* __restrict__ attr,
                        const float* __restrict__ x, const float* __restrict__ W1, int E) {
    __shared__ float Ws[27 * 17];
    for (int j = threadIdx.x; j < 432; j += blockDim.x)
        Ws[(j >> 4) * 17 + (j & 15)] = W1[j];
    __syncthreads();

    int e = blockIdx.x * blockDim.x + threadIdx.x;
    if (e >= E) return;
    int src = __ldcs(ei + e), dst = __ldcs(ei + E + e);

    float f[3]; int i0[3];
    spline_coords_ldcs(attr, e, f, i0);

    float2 xv = *(const float2*)(x + 2 * (size_t)src);

    float msg[8];
#pragma unroll
    for (int o = 0; o < 8; o++) msg[o] = 0.0f;

#pragma unroll
    for (int s = 0; s < 8; s++) {
        int b0 = s & 1, b1 = (s >> 1) & 1, b2 = (s >> 2) & 1;
        float w = (b0 ? f[0] : 1.0f - f[0]) * (b1 ? f[1] : 1.0f - f[1]) * (b2 ? f[2] : 1.0f - f[2]);
        int k = (i0[0] + b0) + 3 * (i0[1] + b1) + 9 * (i0[2] + b2);
        const float* wp = Ws + k * 17;
        float wx = w * xv.x, wy = w * xv.y;
#pragma unroll
        for (int o = 0; o < 8; o++) msg[o] += wx * wp[o] + wy * wp[8 + o];
    }
    float* a = g_s.agg1 + (size_t)dst * 8;
    red_add_v4(a,     msg[0], msg[1], msg[2], msg[3]);
    red_add_v4(a + 4, msg[4], msg[5], msg[6], msg[7]);
    atomicAdd(&g_s.cnt1[dst], 1u);
}

// Level-1 node kernel: h = elu(agg/cnt + x@root1 + b1); max-pool into cluster1 bins.
// Also aggregates cnt1 -> cnt2.
__global__ void k_node1(const float* __restrict__ x, const float* __restrict__ root1,
                        const float* __restrict__ b1, const int* __restrict__ batch,
                        const int* __restrict__ cl1, int N) {
    int n = blockIdx.x * blockDim.x + threadIdx.x;
    if (n >= N) return;
    const float4* ar = (const float4*)(g_s.agg1 + (size_t)n * 8);
    float4 a0 = ar[0], a1 = ar[1];
    float ag[8] = {a0.x, a0.y, a0.z, a0.w, a1.x, a1.y, a1.z, a1.w};
    unsigned c1 = g_s.cnt1[n];
    float inv = 1.0f / fmaxf((float)c1, 1.0f);
    float2 xv = *(const float2*)(x + 2 * (size_t)n);
    int c = cl1[n];
#pragma unroll
    for (int o = 0; o < 8; o++) {
        float h = ag[o] * inv + xv.x * __ldg(root1 + o) + xv.y * __ldg(root1 + 8 + o) + __ldg(b1 + o);
        h = elu1(h);
        atomicMax(&g_s.x1enc[(size_t)c * 8 + o], fenc(h));
    }
    atomicMax(&g_s.batch1[c], batch[n]);
    if (c1) atomicAdd(&g_s.cnt2[c], c1);
}

// Decode x1 + precompute xW2 in fp16: xw2[n1][k][o] = sum_c x1[n1][c] * W2[k][c][o]
__global__ void k_xw2(const float* __restrict__ W2, int N1) {
    __shared__ float Ws[3456];
    for (int j = threadIdx.x; j < 3456; j += blockDim.x) Ws[j] = W2[j];
    __syncthreads();
    int n1 = blockIdx.x * 32 + (threadIdx.x >> 3);
    int q  = threadIdx.x & 7;
    if (n1 >= N1) return;
    float xv[8];
#pragma unroll
    for (int c = 0; c < 8; c++)
        xv[c] = fdec0(g_s.x1enc[(size_t)n1 * 8 + c]);
    if (q < 4)
        *(float2*)(g_x1 + (size_t)n1 * 8 + 2 * q) = make_float2(xv[2 * q], xv[2 * q + 1]);

    __half2* outp = (__half2*)(g_xw2h + (size_t)n1 * 432) + q;
    int o0 = 2 * q;
#pragma unroll
    for (int k = 0; k < 27; k++) {
        float acc0 = 0.0f, acc1 = 0.0f;
#pragma unroll
        for (int c = 0; c < 8; c++) {
            acc0 += xv[c] * Ws[k * 128 + c * 16 + o0];
            acc1 += xv[c] * Ws[k * 128 + c * 16 + o0 + 1];
        }
        outp[k * 8] = __floats2half2_rn(acc0, acc1);
    }
}

// Level-2 edge kernel: 4 THREADS PER EDGE, split by output quarter.
// Lane 4t+q: outputs 4q..4q+3. Each thread: 8 LDG.64 (8B), 4 fp32 accumulators,
// 1 red.v4. Same total lines/sectors/REDG lanes; quarter the dependent chain.
__global__ void k_edge2(const int* __restrict__ ei, const float* __restrict__ attr,
                        const int* __restrict__ cl1, int E) {
    int tid = blockIdx.x * blockDim.x + threadIdx.x;
    int e = tid >> 2;
    int quarter = tid & 3;
    if (e >= E) return;
    int src = __ldcs(ei + e), dst = __ldcs(ei + E + e);
    int s2 = __ldg(cl1 + src), d2 = __ldg(cl1 + dst);

    float f[3]; int i0[3];
    spline_coords_ldcs(attr, e, f, i0);

    float msg[4];
#pragma unroll
    for (int o = 0; o < 4; o++) msg[o] = 0.0f;

    // row k is 32B; this thread's 8B slice at byte offset quarter*8
    const unsigned char* basep = (const unsigned char*)g_xw2h + (size_t)s2 * 864 + quarter * 8;
    float w1a = 1.0f - f[1], w2a = 1.0f - f[2];
    float w0a = 1.0f - f[0], w0b = f[0];
#pragma unroll
    for (int t = 0; t < 4; t++) {
        int b1 = t & 1, b2 = t >> 1;
        float w12 = (b1 ? f[1] : w1a) * (b2 ? f[2] : w2a);
        int kb = i0[0] + 3 * (i0[1] + b1) + 9 * (i0[2] + b2);
        uint2 vA = __ldg((const uint2*)(basep + (size_t)kb * 32));        // corner b0=0
        uint2 vB = __ldg((const uint2*)(basep + (size_t)(kb + 1) * 32));  // corner b0=1
        float wA = w12 * w0a, wB = w12 * w0b;
        acc_h2(msg[0], msg[1], vA.x, wA);
        acc_h2(msg[2], msg[3], vA.y, wA);
        acc_h2(msg[0], msg[1], vB.x, wB);
        acc_h2(msg[2], msg[3], vB.y, wB);
    }
    float* a = g_s.agg2 + (size_t)d2 * 16 + quarter * 4;
    red_add_v4(a, msg[0], msg[1], msg[2], msg[3]);
}

// Level-2 node kernel: h2 = elu(agg2/cnt2 + x1@root2 + b2); max-pool into cluster2 bins
__global__ void k_node2(const float* __restrict__ root2, const float* __restrict__ b2,
                        const int* __restrict__ cl2, int N1) {
    int n1 = blockIdx.x * blockDim.x + threadIdx.x;
    if (n1 >= N1) return;
    const float4* ar = (const float4*)(g_s.agg2 + (size_t)n1 * 16);
    float ag[16];
#pragma unroll
    for (int q = 0; q < 4; q++) {
        float4 v = ar[q];
        ag[q * 4 + 0] = v.x; ag[q * 4 + 1] = v.y; ag[q * 4 + 2] = v.z; ag[q * 4 + 3] = v.w;
    }
    float inv = 1.0f / fmaxf((float)g_s.cnt2[n1], 1.0f);
    float xv[8];
#pragma unroll
    for (int c = 0; c < 8; c++) xv[c] = g_x1[(size_t)n1 * 8 + c];
    int c2 = cl2[n1];
#pragma unroll
    for (int o = 0; o < 16; o++) {
        float h = ag[o] * inv + __ldg(b2 + o);
#pragma unroll
        for (int c = 0; c < 8; c++) h += xv[c] * __ldg(root2 + c * 16 + o);
        h = elu1(h);
        atomicMax(&g_s.x2enc[(size_t)c2 * 16 + o], fenc(h));
    }
    atomicMax(&g_s.batch2[c2], g_s.batch1[n1]);
}

// Decode x2, per-graph sum/count with shared-memory staging
__global__ void k_pool(int N2) {
    __shared__ float    sg[NB * 16];
    __shared__ unsigned sc[NB];
    if (threadIdx.x < NB * 16) sg[threadIdx.x] = 0.0f;
    if (threadIdx.x < NB)      sc[threadIdx.x] = 0u;
    __syncthreads();
    int n2 = blockIdx.x * blockDim.x + threadIdx.x;
    if (n2 < N2) {
        int b = g_s.batch2[n2];
#pragma unroll
        for (int o = 0; o < 16; o++) {
            float v = fdec0(g_s.x2enc[(size_t)n2 * 16 + o]);
            atomicAdd(&sg[b * 16 + o], v);
        }
        atomicAdd(&sc[b], 1u);
    }
    __syncthreads();
    if (threadIdx.x < NB * 16) atomicAdd(&g_s.gsum[threadIdx.x], sg[threadIdx.x]);
    if (threadIdx.x < NB)      atomicAdd(&g_s.gcnt[threadIdx.x], sc[threadIdx.x]);
}

// Final MLP
__global__ void k_mlp(const float* __restrict__ fc1_w, const float* __restrict__ fc1_b,
                      const float* __restrict__ fc2_w, const float* __restrict__ fc2_b,
                      float* __restrict__ out) {
    __shared__ float g[NB * 16];
    __shared__ float h[NB * 64];
    for (int idx = threadIdx.x; idx < NB * 16; idx += blockDim.x) {
        int b = idx / 16;
        g[idx] = g_s.gsum[idx] / fmaxf((float)g_s.gcnt[b], 1.0f);
    }
    __syncthreads();
    int j = threadIdx.x;   // 64 threads
    if (j < 64) {
#pragma unroll
        for (int b = 0; b < NB; b++) {
            float acc = __ldg(fc1_b + j);
#pragma unroll
            for (int c = 0; c < 16; c++) acc += g[b * 16 + c] * __ldg(fc1_w + c * 64 + j);
            h[b * 64 + j] = elu1(acc);
        }
    }
    __syncthreads();
    if (j < NB) {
        float acc = __ldg(fc2_b);
#pragma unroll
        for (int q = 0; q < 64; q++) acc += h[j * 64 + q] * __ldg(fc2_w + q);
        out[j] = elu1(acc);
    }
}

// ---------------- launch ----------------
extern "C" void kernel_launch(void* const* d_in, const int* in_sizes, int n_in,
                              void* d_out, int out_size) {
    const float* x      = (const float*)d_in[0];
    const int*   ei     = (const int*)  d_in[1];
    const float* attr   = (const float*)d_in[2];
    const int*   batch  = (const int*)  d_in[3];
    const int*   cl1    = (const int*)  d_in[4];
    const int*   cl2    = (const int*)  d_in[5];
    const float* W1     = (const float*)d_in[6];
    const float* root1  = (const float*)d_in[7];
    const float* b1     = (const float*)d_in[8];
    const float* W2     = (const float*)d_in[9];
    const float* root2  = (const float*)d_in[10];
    const float* b2     = (const float*)d_in[11];
    const float* fc1_w  = (const float*)d_in[12];
    const float* fc1_b  = (const float*)d_in[13];
    const float* fc2_w  = (const float*)d_in[14];
    const float* fc2_b  = (const float*)d_in[15];
    float* out = (float*)d_out;

    int N  = in_sizes[3];          // 80000
    int E  = in_sizes[1] / 2;      // 1280000
    int N1 = in_sizes[5];          // 40000
    int N2 = N1 / 2;               // 20000

    void* scratch_ptr = nullptr;
    cudaGetSymbolAddress(&scratch_ptr, g_s);
    cudaMemsetAsync(scratch_ptr, 0, sizeof(Scratch));

    const int T = 256;
    k_edge1<<<(E + T - 1) / T, T>>>(ei, attr, x, W1, E);
    k_node1<<<(N + T - 1) / T, T>>>(x, root1, b1, batch, cl1, N);
    k_xw2  <<<(N1 + 31) / 32, T>>>(W2, N1);
    k_edge2<<<(4 * E + T - 1) / T, T>>>(ei, attr, cl1, E);
    k_node2<<<(N1 + T - 1) / T, T>>>(root2, b2, cl2, N1);
    k_pool <<<(N2 + T - 1) / T, T>>>(N2);
    k_mlp  <<<1, 64>>>(fc1_w, fc1_b, fc2_w, fc2_b, out);
}